// round 14
// baseline (speedup 1.0000x reference)
#include <cuda_runtime.h>
#include <cuda_bf16.h>

// Problem geometry: [B=4, 1, D=160, H=160, W=160]
#define NB 4
#define S  160
#define PLANE4  6400               // float4/int4 per (b,d) plane
#define NPLANES 640
#define CHUNK4  800
#define N4      4096000            // total float4 quads
#define BATCH4  1024000            // quads per batch
#define WIN_BLOCKS 1184
#define TOTAL_ELEMS (4.0 * 160.0 * 160.0 * 160.0)

// ---- device scratch (zero at load; k_main's last block re-zeroes) ----
__device__ unsigned char g_winD[NB][8];   // boundary-slab any-flags (0..3 low, 4..7 high)
__device__ unsigned char g_winH[NB][8];
__device__ unsigned char g_winW[NB][8];
__device__ double g_planeSS[NPLANES];     // per-plane sum of (p-t)^2
__device__ float  g_row159[NPLANES];      // per-plane sum over row h=159
__device__ float  g_col159[NPLANES];      // per-plane sum over col w=159
__device__ float  g_e1599[NPLANES];       // per-plane element (159,159)
__device__ unsigned g_done;

// Exact f32 replication of the reference bbox math (mn<0 -> empty box).
__device__ __forceinline__ void bbox_from(int mn, int mx, int* lo, int* hi) {
    if (mn < 0) { *lo = 0; *hi = 0; return; }
    float c = ((float)mx + (float)mn) * 0.5f;
    float e = ((float)mx - (float)mn + 1.0f) * 0.5f * 1.2f;   // EXPAND
    *lo = (int)fmaxf(0.0f, floorf(c - e));
    *hi = (int)fminf((float)(S - 1), floorf(c + e));          // EXCLUSIVE
}

// ===================== kernel 1: mask boundary windows ONLY =================
// 1536 grid-stride items over 1184 blocks:
//   [0,256):    D-window chunks — plane d in {0..3,156..159}, 800 int4 each
//   [256,896):  H-window plane items — rows {0..3,156..159} (320 int4)
//   [896,1536): W-window plane items — first/last int4 of each row (320 loads)
// All flag stores are benign races (every writer stores 1).
__global__ __launch_bounds__(256) void k_win(const int* __restrict__ mask) {
    const int tid = threadIdx.x;
    for (int item = blockIdx.x; item < 1536; item += WIN_BLOCKS) {
        if (item < 256) {
            int bb   = item >> 6;
            int wp   = (item >> 3) & 7;
            int part = item & 7;
            int dd   = (wp < 4) ? wp : 152 + wp;
            const int4* MD = (const int4*)mask + (size_t)(bb * S + dd) * PLANE4 + part * CHUNK4;
            int o = 0;
            for (int j = tid; j < CHUNK4; j += 256) {
                int4 v = MD[j];
                o |= v.x | v.y | v.z | v.w;
            }
            if (__syncthreads_or(o)) { if (tid == 0) g_winD[bb][wp] = 1; }
        } else if (item < 896) {
            int p = item - 256;
            int b = p / S;
            const int4* M = (const int4*)mask + (size_t)p * PLANE4;
            for (int j = tid; j < 320; j += 256) {
                int q    = (j < 160) ? j : 6240 + (j - 160);
                int slot = (j < 160) ? (j / 40) : 4 + (j - 160) / 40;
                int4 v = M[q];
                if (v.x | v.y | v.z | v.w) g_winH[b][slot] = 1;
            }
        } else {
            int p = item - 896;
            int b = p / S;
            const int4* M = (const int4*)mask + (size_t)p * PLANE4;
            for (int j = tid; j < 320; j += 256) {
                int r    = (j < 160) ? j : j - 160;
                int side = (j < 160) ? 0 : 1;
                int4 v = M[r * 40 + side * 39];
                if (v.x) g_winW[b][side * 4 + 0] = 1;
                if (v.y) g_winW[b][side * 4 + 1] = 1;
                if (v.z) g_winW[b][side * 4 + 2] = 1;
                if (v.w) g_winW[b][side * 4 + 3] = 1;
            }
        }
    }
}

// ===================== kernel 2: pure stream SS + tables; finalize ==========
// One block per (b,d) plane, 640 x 256 — the best-measured BW shape (R1:
// 5.08 TB/s). NO mask access in the stream. Accumulates plane SS plus the
// h=159 / w=159 / (159,159) slabs. Last-done block: if every axis has fg in
// both 4-wide boundary windows (k_win flags; visible via stream ordering),
// the reference box is PROVABLY [0,159)^3 (mn<=3, mx>=156 => c-e<0,
// c+e>159), so the ROI complement is the three index-159 slabs and the loss
// follows by inclusion-exclusion over the per-plane tables. Otherwise an
// exact single-block fallback runs (correct for ALL inputs).
__global__ __launch_bounds__(256) void k_main(const float* __restrict__ pred,
                                              const float* __restrict__ truth,
                                              const int*   __restrict__ mask,
                                              float* __restrict__ out) {
    __shared__ double wAcc[8], wRow[8], wCol[8];
    __shared__ int sLast;
    __shared__ unsigned char sFlags[96];
    __shared__ double sRed[8][8];

    const int p   = blockIdx.x;          // 0..639
    const int tid = threadIdx.x;

    const float4* P = (const float4*)pred  + (size_t)p * PLANE4;
    const float4* T = (const float4*)truth + (size_t)p * PLANE4;

    bool isW[5];                         // (i % 40 == 39): j-invariant per slot
    #pragma unroll
    for (int s = 0; s < 5; s++) isW[s] = (((tid + 16 * s) % 40) == 39);

    float acc = 0.0f, accRow = 0.0f, accCol = 0.0f, e1599 = 0.0f;
    #pragma unroll 1
    for (int j = 0; j < 5; j++) {
        #pragma unroll
        for (int s = 0; s < 5; s++) {
            int i = tid + 256 * (j * 5 + s);
            float4 pv = P[i];
            float4 tv = T[i];
            float dx = pv.x - tv.x, dy = pv.y - tv.y;
            float dz = pv.z - tv.z, dw = pv.w - tv.w;
            float q = dx * dx;
            q = fmaf(dy, dy, q);
            q = fmaf(dz, dz, q);
            q = fmaf(dw, dw, q);
            acc += q;
            if (i >= 6360) accRow += q;           // row h = 159
            if (isW[s]) {                          // column w = 159 (.w lane)
                float w2 = dw * dw;
                accCol += w2;
                if (i == 6399) e1599 = w2;         // (159,159)
            }
        }
    }

    // ---- reduce; store per-plane tables ----
    #pragma unroll
    for (int off = 16; off > 0; off >>= 1) {
        acc    += __shfl_xor_sync(0xFFFFFFFFu, acc,    off);
        accRow += __shfl_xor_sync(0xFFFFFFFFu, accRow, off);
        accCol += __shfl_xor_sync(0xFFFFFFFFu, accCol, off);
    }
    const int lane = tid & 31, wid = tid >> 5;
    if (lane == 0) {
        wAcc[wid] = (double)acc;
        wRow[wid] = (double)accRow;
        wCol[wid] = (double)accCol;
    }
    __syncthreads();
    if (tid == 0) {
        double sa = 0.0, sr = 0.0, sc = 0.0;
        #pragma unroll
        for (int w = 0; w < 8; w++) { sa += wAcc[w]; sr += wRow[w]; sc += wCol[w]; }
        g_planeSS[p] = sa;
        g_row159[p]  = (float)sr;
        g_col159[p]  = (float)sc;
    }
    if (tid == 255) g_e1599[p] = e1599;           // owns i = 6399

    // ---- threadFenceReduction ticket: last-done block finalizes ----
    __threadfence();
    __syncthreads();
    if (tid == 0) sLast = (atomicAdd(&g_done, 1u) == (unsigned)(NPLANES - 1));
    __syncthreads();
    if (!sLast) return;

    // parallel window-flag fetch (flags written by k_win; stream-ordered)
    if (tid < 32)      sFlags[tid] = ((const unsigned char*)g_winD)[tid];
    else if (tid < 64) sFlags[tid] = ((const unsigned char*)g_winH)[tid - 32];
    else if (tid < 96) sFlags[tid] = ((const unsigned char*)g_winW)[tid - 64];
    __syncthreads();

    bool resolved = true;
    #pragma unroll
    for (int bb = 0; bb < NB; bb++) {
        #pragma unroll
        for (int ax = 0; ax < 3; ax++) {
            const unsigned char* f = &sFlags[ax * 32 + bb * 8];
            int loAny = f[0] | f[1] | f[2] | f[3];
            int hiAny = f[4] | f[5] | f[6] | f[7];
            if (!loAny || !hiAny) resolved = false;
        }
    }

    if (resolved) {
        // box = [0,159)^3 for every batch: inclusion-exclusion over tables
        double v[8];                     // ssAll, D, H, W, DH, DW, HW, DHW
        #pragma unroll
        for (int q = 0; q < 8; q++) v[q] = 0.0;
        for (int pp = tid; pp < NPLANES; pp += 256) {
            double ps = g_planeSS[pp];
            double r  = (double)g_row159[pp];
            double cc = (double)g_col159[pp];
            double e  = (double)g_e1599[pp];
            v[0] += ps; v[2] += r; v[3] += cc; v[6] += e;
            if ((pp % S) == S - 1) { v[1] += ps; v[4] += r; v[5] += cc; v[7] += e; }
        }
        #pragma unroll
        for (int q = 0; q < 8; q++) {
            #pragma unroll
            for (int off = 16; off > 0; off >>= 1)
                v[q] += __shfl_xor_sync(0xFFFFFFFFu, v[q], off);
        }
        if (lane == 0) {
            #pragma unroll
            for (int q = 0; q < 8; q++) sRed[wid][q] = v[q];
        }
        __syncthreads();
        if (tid == 0) {
            double t[8];
            #pragma unroll
            for (int q = 0; q < 8; q++) {
                t[q] = 0.0;
                #pragma unroll
                for (int w = 0; w < 8; w++) t[q] += sRed[w][q];
            }
            double ssOut = t[1] + t[2] + t[3] - t[4] - t[5] - t[6] + t[7];
            out[0] = (float)((t[0] - 0.99 * ssOut) / TOTAL_ELEMS);
        }
    } else {
        // ---- exact single-block fallback (never taken for dense masks) ----
        __shared__ int sMn[12], sMx[12];
        if (tid < 12) { sMn[tid] = S; sMx[tid] = -1; }
        __syncthreads();

        const int4* MM = (const int4*)mask;
        for (int i = tid; i < N4; i += 256) {
            int4 v = MM[i];
            if (v.x | v.y | v.z | v.w) {
                int bb  = i / BATCH4;
                int rem = i - bb * BATCH4;
                int d   = rem / PLANE4;
                int ip  = rem - d * PLANE4;
                int h   = ip / 40;
                int w0  = (ip - h * 40) * 4;
                atomicMin(&sMn[bb * 3 + 0], d); atomicMax(&sMx[bb * 3 + 0], d);
                atomicMin(&sMn[bb * 3 + 1], h); atomicMax(&sMx[bb * 3 + 1], h);
                if (v.x) { atomicMin(&sMn[bb * 3 + 2], w0 + 0); atomicMax(&sMx[bb * 3 + 2], w0 + 0); }
                if (v.y) { atomicMin(&sMn[bb * 3 + 2], w0 + 1); atomicMax(&sMx[bb * 3 + 2], w0 + 1); }
                if (v.z) { atomicMin(&sMn[bb * 3 + 2], w0 + 2); atomicMax(&sMx[bb * 3 + 2], w0 + 2); }
                if (v.w) { atomicMin(&sMn[bb * 3 + 2], w0 + 3); atomicMax(&sMx[bb * 3 + 2], w0 + 3); }
            }
        }
        __syncthreads();

        __shared__ int sLo[12], sHi[12];
        if (tid < 12) {
            int mn = (sMx[tid] >= 0) ? sMn[tid] : -1;
            int lo, hi;
            bbox_from(mn, sMx[tid], &lo, &hi);
            sLo[tid] = lo; sHi[tid] = hi;
        }
        __syncthreads();

        const float4* PP = (const float4*)pred;
        const float4* TT = (const float4*)truth;
        float fa = 0.0f;
        for (int i = tid; i < N4; i += 256) {
            float4 pv = PP[i];
            float4 tv = TT[i];
            int bb  = i / BATCH4;
            int rem = i - bb * BATCH4;
            int d   = rem / PLANE4;
            int ip  = rem - d * PLANE4;
            int h   = ip / 40;
            int w0  = (ip - h * 40) * 4;
            bool inDH = (d >= sLo[bb * 3]) && (d < sHi[bb * 3]) &&
                        (h >= sLo[bb * 3 + 1]) && (h < sHi[bb * 3 + 1]);
            int loW = sLo[bb * 3 + 2], hiW = sHi[bb * 3 + 2];
            float wx = (inDH && w0 + 0 >= loW && w0 + 0 < hiW) ? 1.0f : 0.01f;
            float wy = (inDH && w0 + 1 >= loW && w0 + 1 < hiW) ? 1.0f : 0.01f;
            float wz = (inDH && w0 + 2 >= loW && w0 + 2 < hiW) ? 1.0f : 0.01f;
            float ww = (inDH && w0 + 3 >= loW && w0 + 3 < hiW) ? 1.0f : 0.01f;
            float dx = pv.x - tv.x, dy = pv.y - tv.y, dz = pv.z - tv.z, dw = pv.w - tv.w;
            fa = fmaf(wx * dx, dx, fa);
            fa = fmaf(wy * dy, dy, fa);
            fa = fmaf(wz * dz, dz, fa);
            fa = fmaf(ww * dw, dw, fa);
        }
        #pragma unroll
        for (int off = 16; off > 0; off >>= 1)
            fa += __shfl_xor_sync(0xFFFFFFFFu, fa, off);
        if (lane == 0) wAcc[wid] = (double)fa;
        __syncthreads();
        if (tid == 0) {
            double s = 0.0;
            #pragma unroll
            for (int w = 0; w < 8; w++) s += wAcc[w];
            out[0] = (float)(s / TOTAL_ELEMS);
        }
    }

    // ---- reset scratch so the next graph replay starts from a clean state --
    __syncthreads();
    if (tid < 32) {
        ((unsigned char*)g_winD)[tid] = 0;
        ((unsigned char*)g_winH)[tid] = 0;
        ((unsigned char*)g_winW)[tid] = 0;
    }
    if (tid == 0) g_done = 0u;
}

extern "C" void kernel_launch(void* const* d_in, const int* in_sizes, int n_in,
                              void* d_out, int out_size) {
    const float* y_pred = (const float*)d_in[0];
    const float* y_true = (const float*)d_in[1];
    const int*   mask   = (const int*)d_in[2];
    float* out = (float*)d_out;

    k_win<<<WIN_BLOCKS, 256>>>(mask);
    k_main<<<NPLANES, 256>>>(y_pred, y_true, mask, out);
}

// round 15
// speedup vs baseline: 1.4533x; 1.4533x over previous
#include <cuda_runtime.h>
#include <cuda_bf16.h>

// Problem geometry: [B=4, 1, D=160, H=160, W=160]
#define NB 4
#define S  160
#define PLANE4  6400               // float4/int4 per (b,d) plane
#define NPLANES 640
#define N4      4096000            // total float4 quads
#define BATCH4  1024000            // quads per batch
#define TOTAL_ELEMS (4.0 * 160.0 * 160.0 * 160.0)

// ---- device scratch (zero at load; last block re-zeroes flags/counter) ----
__device__ unsigned char g_winD[NB][8];   // axis-end fg flags (slot 0 = low, 4 = high)
__device__ unsigned char g_winH[NB][8];
__device__ unsigned char g_winW[NB][8];
__device__ double g_planeSS[NPLANES];     // per-plane sum of (p-t)^2
__device__ float  g_row159[NPLANES];      // per-plane sum over row h=159
__device__ float  g_col159[NPLANES];      // per-plane sum over col w=159
__device__ float  g_e1599[NPLANES];       // per-plane element (159,159)
__device__ unsigned g_done;

// Exact f32 replication of the reference bbox math (mn<0 -> empty box).
__device__ __forceinline__ void bbox_from(int mn, int mx, int* lo, int* hi) {
    if (mn < 0) { *lo = 0; *hi = 0; return; }
    float c = ((float)mx + (float)mn) * 0.5f;
    float e = ((float)mx - (float)mn + 1.0f) * 0.5f * 1.2f;   // EXPAND
    *lo = (int)fmaxf(0.0f, floorf(c - e));
    *hi = (int)fminf((float)(S - 1), floorf(c + e));          // EXCLUSIVE
}

// ============================================================================
// Single kernel. One block per (b,d) plane, 640 x 256 (R1's best-measured
// shape). Hot loop is a PURE unweighted-SS stream (1 accumulator, 2 LDG.128 +
// 8 FP per iter). The h=159 / w=159 / (159,159) slab sums are recomputed in a
// ~200-quad L2-hot epilogue. Blocks 0..23 additionally SAMPLE 256 int4 from
// one (batch, axis, side) mask boundary region: any foreground voxel there
// proves that axis end (mn<=3 or mx>=156). If all 24 ends are proven, the
// reference box is exactly [0,159)^3 for every batch (mn<=3, mx>=156 =>
// c-e<0 and c+e>159), so the ROI complement is the three index-159 slabs and
// the loss follows by inclusion-exclusion over the per-plane tables. Any
// unproven end (impossible for dense masks, P=16^-256) -> exact single-block
// fallback. Last-done block finalizes and resets scratch for graph replay.
// ============================================================================
__global__ __launch_bounds__(256) void k_all(const float* __restrict__ pred,
                                             const float* __restrict__ truth,
                                             const int*   __restrict__ mask,
                                             float* __restrict__ out) {
    __shared__ double wAcc[8], wRow[8], wCol[8];
    __shared__ int sLast;
    __shared__ unsigned char sFlags[96];
    __shared__ double sRed[8][8];

    const int p   = blockIdx.x;          // 0..639
    const int tid = threadIdx.x;

    // ---- boundary-end sampling (blocks 0..23 only; one extra round trip) ---
    if (blockIdx.x < 24) {
        int b    = blockIdx.x / 6;
        int r    = blockIdx.x % 6;
        int ax   = r >> 1;               // 0=D, 1=H, 2=W
        int side = r & 1;                // 0=low end, 1=high end
        int plane, quad;
        if (ax == 0) {                   // fg with d in {0..3} / {156..159}
            int d = (side ? 156 : 0) + (tid & 3);
            plane = b * S + d;
            quad  = (tid * 25) % PLANE4;
        } else if (ax == 1) {            // fg with h in {0..3} / {156..159}
            plane = b * S + (tid % S);
            quad  = (side ? 6240 : 0) + ((tid * 37) % 160);
        } else {                         // fg with w in {0..3} / {156..159}
            plane = b * S + (tid % S);
            quad  = ((tid * 13) % 160) * 40 + (side ? 39 : 0);
        }
        int4 v = ((const int4*)mask)[(size_t)plane * PLANE4 + quad];
        int found = __syncthreads_or(v.x | v.y | v.z | v.w);
        if (tid == 0 && found) {
            if (ax == 0)      g_winD[b][side * 4] = 1;
            else if (ax == 1) g_winH[b][side * 4] = 1;
            else              g_winW[b][side * 4] = 1;
        }
    }

    // ---- pure streaming SS over this plane (25 iters, R1 shape) ----
    const float4* P = (const float4*)pred  + (size_t)p * PLANE4;
    const float4* T = (const float4*)truth + (size_t)p * PLANE4;

    float acc = 0.0f;
    #pragma unroll 5
    for (int i = tid; i < PLANE4; i += 256) {
        float4 pv = P[i];
        float4 tv = T[i];
        float dx = pv.x - tv.x, dy = pv.y - tv.y;
        float dz = pv.z - tv.z, dw = pv.w - tv.w;
        acc = fmaf(dx, dx, acc);
        acc = fmaf(dy, dy, acc);
        acc = fmaf(dz, dz, acc);
        acc = fmaf(dw, dw, acc);
    }

    // ---- L2-hot slab epilogue: row h=159 (40 quads), col w=159 (160 .w) ----
    float accRow = 0.0f, accCol = 0.0f, e1599 = 0.0f;
    if (tid < 160) {                     // col: quad tid*40+39, take .w lane
        int i = tid * 40 + 39;
        float dw = P[i].w - T[i].w;
        accCol = dw * dw;
    } else if (tid < 200) {              // row: quads 6360..6399, full quad
        int i = 6360 + (tid - 160);
        float4 pv = P[i];
        float4 tv = T[i];
        float dx = pv.x - tv.x, dy = pv.y - tv.y;
        float dz = pv.z - tv.z, dw = pv.w - tv.w;
        accRow = fmaf(dx, dx, fmaf(dy, dy, fmaf(dz, dz, dw * dw)));
        if (tid == 199) e1599 = dw * dw; // quad 6399 .w = (159,159)
    }

    // ---- reduce 3 values; store per-plane tables ----
    #pragma unroll
    for (int off = 16; off > 0; off >>= 1) {
        acc    += __shfl_xor_sync(0xFFFFFFFFu, acc,    off);
        accRow += __shfl_xor_sync(0xFFFFFFFFu, accRow, off);
        accCol += __shfl_xor_sync(0xFFFFFFFFu, accCol, off);
    }
    const int lane = tid & 31, wid = tid >> 5;
    if (lane == 0) {
        wAcc[wid] = (double)acc;
        wRow[wid] = (double)accRow;
        wCol[wid] = (double)accCol;
    }
    __syncthreads();
    if (tid == 0) {
        double sa = 0.0, sr = 0.0, sc = 0.0;
        #pragma unroll
        for (int w = 0; w < 8; w++) { sa += wAcc[w]; sr += wRow[w]; sc += wCol[w]; }
        g_planeSS[p] = sa;
        g_row159[p]  = (float)sr;
        g_col159[p]  = (float)sc;
    }
    if (tid == 199) g_e1599[p] = e1599;

    // ---- threadFenceReduction ticket: last-done block finalizes ----
    __threadfence();
    __syncthreads();
    if (tid == 0) sLast = (atomicAdd(&g_done, 1u) == (unsigned)(NPLANES - 1));
    __syncthreads();
    if (!sLast) return;

    // parallel window-flag fetch
    if (tid < 32)      sFlags[tid] = ((const unsigned char*)g_winD)[tid];
    else if (tid < 64) sFlags[tid] = ((const unsigned char*)g_winH)[tid - 32];
    else if (tid < 96) sFlags[tid] = ((const unsigned char*)g_winW)[tid - 64];
    __syncthreads();

    bool resolved = true;
    #pragma unroll
    for (int bb = 0; bb < NB; bb++) {
        #pragma unroll
        for (int ax = 0; ax < 3; ax++) {
            const unsigned char* f = &sFlags[ax * 32 + bb * 8];
            int loAny = f[0] | f[1] | f[2] | f[3];
            int hiAny = f[4] | f[5] | f[6] | f[7];
            if (!loAny || !hiAny) resolved = false;
        }
    }

    if (resolved) {
        // box = [0,159)^3 for every batch: inclusion-exclusion over tables
        double v[8];                     // ssAll, D, H, W, DH, DW, HW, DHW
        #pragma unroll
        for (int q = 0; q < 8; q++) v[q] = 0.0;
        for (int pp = tid; pp < NPLANES; pp += 256) {
            double ps = g_planeSS[pp];
            double r  = (double)g_row159[pp];
            double cc = (double)g_col159[pp];
            double e  = (double)g_e1599[pp];
            v[0] += ps; v[2] += r; v[3] += cc; v[6] += e;
            if ((pp % S) == S - 1) { v[1] += ps; v[4] += r; v[5] += cc; v[7] += e; }
        }
        #pragma unroll
        for (int q = 0; q < 8; q++) {
            #pragma unroll
            for (int off = 16; off > 0; off >>= 1)
                v[q] += __shfl_xor_sync(0xFFFFFFFFu, v[q], off);
        }
        if (lane == 0) {
            #pragma unroll
            for (int q = 0; q < 8; q++) sRed[wid][q] = v[q];
        }
        __syncthreads();
        if (tid == 0) {
            double t[8];
            #pragma unroll
            for (int q = 0; q < 8; q++) {
                t[q] = 0.0;
                #pragma unroll
                for (int w = 0; w < 8; w++) t[q] += sRed[w][q];
            }
            double ssOut = t[1] + t[2] + t[3] - t[4] - t[5] - t[6] + t[7];
            out[0] = (float)((t[0] - 0.99 * ssOut) / TOTAL_ELEMS);
        }
    } else {
        // ---- exact single-block fallback (P = 16^-256 per end; correctness
        //      path for arbitrary masks) ----
        __shared__ int sMn[12], sMx[12];
        if (tid < 12) { sMn[tid] = S; sMx[tid] = -1; }
        __syncthreads();

        const int4* MM = (const int4*)mask;
        for (int i = tid; i < N4; i += 256) {
            int4 v = MM[i];
            if (v.x | v.y | v.z | v.w) {
                int bb  = i / BATCH4;
                int rem = i - bb * BATCH4;
                int d   = rem / PLANE4;
                int ip  = rem - d * PLANE4;
                int h   = ip / 40;
                int w0  = (ip - h * 40) * 4;
                atomicMin(&sMn[bb * 3 + 0], d); atomicMax(&sMx[bb * 3 + 0], d);
                atomicMin(&sMn[bb * 3 + 1], h); atomicMax(&sMx[bb * 3 + 1], h);
                if (v.x) { atomicMin(&sMn[bb * 3 + 2], w0 + 0); atomicMax(&sMx[bb * 3 + 2], w0 + 0); }
                if (v.y) { atomicMin(&sMn[bb * 3 + 2], w0 + 1); atomicMax(&sMx[bb * 3 + 2], w0 + 1); }
                if (v.z) { atomicMin(&sMn[bb * 3 + 2], w0 + 2); atomicMax(&sMx[bb * 3 + 2], w0 + 2); }
                if (v.w) { atomicMin(&sMn[bb * 3 + 2], w0 + 3); atomicMax(&sMx[bb * 3 + 2], w0 + 3); }
            }
        }
        __syncthreads();

        __shared__ int sLo[12], sHi[12];
        if (tid < 12) {
            int mn = (sMx[tid] >= 0) ? sMn[tid] : -1;
            int lo, hi;
            bbox_from(mn, sMx[tid], &lo, &hi);
            sLo[tid] = lo; sHi[tid] = hi;
        }
        __syncthreads();

        const float4* PP = (const float4*)pred;
        const float4* TT = (const float4*)truth;
        float fa = 0.0f;
        for (int i = tid; i < N4; i += 256) {
            float4 pv = PP[i];
            float4 tv = TT[i];
            int bb  = i / BATCH4;
            int rem = i - bb * BATCH4;
            int d   = rem / PLANE4;
            int ip  = rem - d * PLANE4;
            int h   = ip / 40;
            int w0  = (ip - h * 40) * 4;
            bool inDH = (d >= sLo[bb * 3]) && (d < sHi[bb * 3]) &&
                        (h >= sLo[bb * 3 + 1]) && (h < sHi[bb * 3 + 1]);
            int loW = sLo[bb * 3 + 2], hiW = sHi[bb * 3 + 2];
            float wx = (inDH && w0 + 0 >= loW && w0 + 0 < hiW) ? 1.0f : 0.01f;
            float wy = (inDH && w0 + 1 >= loW && w0 + 1 < hiW) ? 1.0f : 0.01f;
            float wz = (inDH && w0 + 2 >= loW && w0 + 2 < hiW) ? 1.0f : 0.01f;
            float ww = (inDH && w0 + 3 >= loW && w0 + 3 < hiW) ? 1.0f : 0.01f;
            float dx = pv.x - tv.x, dy = pv.y - tv.y, dz = pv.z - tv.z, dw = pv.w - tv.w;
            fa = fmaf(wx * dx, dx, fa);
            fa = fmaf(wy * dy, dy, fa);
            fa = fmaf(wz * dz, dz, fa);
            fa = fmaf(ww * dw, dw, fa);
        }
        #pragma unroll
        for (int off = 16; off > 0; off >>= 1)
            fa += __shfl_xor_sync(0xFFFFFFFFu, fa, off);
        if (lane == 0) wAcc[wid] = (double)fa;
        __syncthreads();
        if (tid == 0) {
            double s = 0.0;
            #pragma unroll
            for (int w = 0; w < 8; w++) s += wAcc[w];
            out[0] = (float)(s / TOTAL_ELEMS);
        }
    }

    // ---- reset scratch so the next graph replay starts from a clean state --
    __syncthreads();
    if (tid < 32) {
        ((unsigned char*)g_winD)[tid] = 0;
        ((unsigned char*)g_winH)[tid] = 0;
        ((unsigned char*)g_winW)[tid] = 0;
    }
    if (tid == 0) g_done = 0u;
}

extern "C" void kernel_launch(void* const* d_in, const int* in_sizes, int n_in,
                              void* d_out, int out_size) {
    const float* y_pred = (const float*)d_in[0];
    const float* y_true = (const float*)d_in[1];
    const int*   mask   = (const int*)d_in[2];
    float* out = (float*)d_out;

    k_all<<<NPLANES, 256>>>(y_pred, y_true, mask, out);
}

// round 16
// speedup vs baseline: 1.5747x; 1.0835x over previous
#include <cuda_runtime.h>
#include <cuda_bf16.h>

// Problem geometry: [B=4, 1, D=160, H=160, W=160]
#define NB 4
#define S  160
#define PLANE4  6400               // float4/int4 per (b,d) plane
#define NCHUNKS 5120               // 8 chunks per plane, 20 rows x 40 quads
#define CHUNK4  800
#define NBLK    (148 * 12)         // 1776 blocks = exactly one wave at 12/SM
#define NT      160
#define N4      4096000            // total float4 quads
#define BATCH4  1024000            // quads per batch
#define TOTAL_ELEMS (4.0 * 160.0 * 160.0 * 160.0)

// ---- device scratch (zero at load; finalizer re-zeroes for graph replay) ---
__device__ unsigned char g_end[NB][6];  // axis-end fg proof flags [b][axis*2+side]
__device__ double g_ss8[8];             // All, D, H, W, DH, DW, HW, DHW
__device__ unsigned g_done;

// Exact f32 replication of the reference bbox math (mn<0 -> empty box).
__device__ __forceinline__ void bbox_from(int mn, int mx, int* lo, int* hi) {
    if (mn < 0) { *lo = 0; *hi = 0; return; }
    float c = ((float)mx + (float)mn) * 0.5f;
    float e = ((float)mx - (float)mn + 1.0f) * 0.5f * 1.2f;   // EXPAND
    *lo = (int)fmaxf(0.0f, floorf(c - e));
    *hi = (int)fminf((float)(S - 1), floorf(c + e));          // EXCLUSIVE
}

// ============================================================================
// Single kernel, 1776 x 160 (12 blocks/SM -> 93.75% occ, one wave).
// Grid-stride over 5120 chunks (20 rows x 40 quads). Thread owns fixed column
// c = tid%40 and row-group rg = tid/40; all slab predicates are fixed:
//   w=159  <=> c==39 (.w lane, every k)
//   h=159  <=> part==7 && rg==3 && k==4 (captured once)
//   d=159  <=> plane%160==159 (chunk-uniform; 32 chunks)
// Blocks 0..23 additionally SAMPLE 160 int4 from one (batch, axis, side) mask
// boundary region: any fg there proves that axis end (mn<=3 / mx>=156). If
// all 24 ends are proven, the reference box is exactly [0,159)^3 for every
// batch (mn<=3, mx>=156 => c-e<0, c+e>159), so the ROI complement is the
// three index-159 slabs and loss = (SS_all - 0.99*SS_out)/N with SS_out by
// inclusion-exclusion over g_ss8. Any unproven end (P<=16^-160 per end for
// dense masks) -> exact single-block fallback. Last-done block finalizes and
// resets scratch.
// ============================================================================
__global__ __launch_bounds__(NT, 12) void k_all(const float* __restrict__ pred,
                                                const float* __restrict__ truth,
                                                const int*   __restrict__ mask,
                                                float* __restrict__ out) {
    __shared__ float  sX[6];             // D, DH, DW, DHW, H, HW (rare terms)
    __shared__ double sOut[8];
    __shared__ int sLast;
    __shared__ unsigned char sF[24];
    __shared__ double wRed[5];

    const int tid = threadIdx.x;
    const int c   = tid % 40;
    const int rg  = tid / 40;            // 0..3
    const bool c39 = (c == 39);

    if (tid < 6) sX[tid] = 0.0f;
    __syncthreads();

    // ---- boundary-end sampling (blocks 0..23; one extra round trip) ----
    if (blockIdx.x < 24) {
        int b    = blockIdx.x / 6;
        int r    = blockIdx.x % 6;
        int ax   = r >> 1;               // 0=D, 1=H, 2=W
        int side = r & 1;                // 0=low end, 1=high end
        int plane, quad;
        if (ax == 0) {                   // fg with d in {0..3} / {156..159}
            int d = (side ? 156 : 0) + (tid & 3);
            plane = b * S + d;
            quad  = (tid * 41) % PLANE4;
        } else if (ax == 1) {            // fg with h in {0..3} / {156..159}
            plane = b * S + (tid % S);
            quad  = (side ? 6240 : 0) + ((tid * 37) % 160);
        } else {                         // fg with w in {0..3} / {156..159}
            plane = b * S + (tid % S);
            quad  = ((tid * 13) % 160) * 40 + (side ? 39 : 0);
        }
        int4 v = ((const int4*)mask)[(size_t)plane * PLANE4 + quad];
        int found = __syncthreads_or(v.x | v.y | v.z | v.w);
        if (tid == 0 && found) g_end[b][r] = 1;
    }

    // ---- streaming pass over chunks ----
    float aAll = 0.0f, aW = 0.0f;
    for (int chunk = blockIdx.x; chunk < NCHUNKS; chunk += NBLK) {
        const int plane = chunk >> 3;
        const int part  = chunk & 7;
        const int base  = plane * PLANE4 + part * CHUNK4 + tid;
        const float4* P = (const float4*)pred  + base;
        const float4* T = (const float4*)truth + base;

        float qa = 0.0f, qc = 0.0f, q4 = 0.0f, w24 = 0.0f;
        #pragma unroll
        for (int k = 0; k < 5; k++) {
            float4 pv = P[160 * k];
            float4 tv = T[160 * k];
            float dx = pv.x - tv.x, dy = pv.y - tv.y;
            float dz = pv.z - tv.z, dw = pv.w - tv.w;
            float q = dx * dx;
            q = fmaf(dy, dy, q);
            q = fmaf(dz, dz, q);
            float w2 = dw * dw;
            q += w2;
            qa += q;
            if (c39) qc += w2;           // column w = 159
            if (k == 4) { q4 = q; w24 = w2; }
        }
        aAll += qa;
        if (c39) aW += qc;

        const bool isRow = (part == 7) && (rg == 3);   // k=4 row is h=159
        const bool isD   = (plane % S) == (S - 1);     // plane d=159
        if (isRow) {
            atomicAdd(&sX[4], q4);                     // H
            if (c39) atomicAdd(&sX[5], w24);           // HW
        }
        if (isD) {
            atomicAdd(&sX[0], qa);                     // D
            if (c39) atomicAdd(&sX[2], qc);            // DW
            if (isRow) {
                atomicAdd(&sX[1], q4);                 // DH
                if (c39) atomicAdd(&sX[3], w24);       // DHW
            }
        }
    }

    // ---- block reduce aAll / aW; publish 8 values via global double atomics -
    #pragma unroll
    for (int off = 16; off > 0; off >>= 1) {
        aAll += __shfl_xor_sync(0xFFFFFFFFu, aAll, off);
        aW   += __shfl_xor_sync(0xFFFFFFFFu, aW,   off);
    }
    const int lane = tid & 31, wid = tid >> 5;
    __shared__ float wA[5], wW[5];
    if (lane == 0) { wA[wid] = aAll; wW[wid] = aW; }
    __syncthreads();
    if (tid == 0) {
        float sa = 0.0f, sw = 0.0f;
        #pragma unroll
        for (int w = 0; w < 5; w++) { sa += wA[w]; sw += wW[w]; }
        sOut[0] = (double)sa;            // All
        sOut[1] = (double)sX[0];         // D
        sOut[2] = (double)sX[4];         // H
        sOut[3] = (double)sw;            // W
        sOut[4] = (double)sX[1];         // DH
        sOut[5] = (double)sX[2];         // DW
        sOut[6] = (double)sX[5];         // HW
        sOut[7] = (double)sX[3];         // DHW
    }
    __syncthreads();
    if (tid < 8) atomicAdd(&g_ss8[tid], sOut[tid]);

    // ---- threadFenceReduction ticket: last-done block finalizes ----
    __threadfence();
    __syncthreads();
    if (tid == 0) sLast = (atomicAdd(&g_done, 1u) == (unsigned)(NBLK - 1));
    __syncthreads();
    if (!sLast) return;

    // parallel flag + table fetch
    if (tid < 24) sF[tid] = ((volatile unsigned char*)g_end)[tid];
    __syncthreads();
    int ok = 1;
    #pragma unroll
    for (int i = 0; i < 24; i++) ok &= sF[i];

    if (ok) {
        if (tid < 8) sOut[tid] = g_ss8[tid];
        __syncthreads();
        if (tid == 0) {
            double ssOut = sOut[1] + sOut[2] + sOut[3]
                         - sOut[4] - sOut[5] - sOut[6] + sOut[7];
            out[0] = (float)((sOut[0] - 0.99 * ssOut) / TOTAL_ELEMS);
        }
    } else {
        // ---- exact single-block fallback (correct for ARBITRARY masks) ----
        __shared__ int sMn[12], sMx[12];
        if (tid < 12) { sMn[tid] = S; sMx[tid] = -1; }
        __syncthreads();

        const int4* MM = (const int4*)mask;
        for (int i = tid; i < N4; i += NT) {
            int4 v = MM[i];
            if (v.x | v.y | v.z | v.w) {
                int bb  = i / BATCH4;
                int rem = i - bb * BATCH4;
                int d   = rem / PLANE4;
                int ip  = rem - d * PLANE4;
                int h   = ip / 40;
                int w0  = (ip - h * 40) * 4;
                atomicMin(&sMn[bb * 3 + 0], d); atomicMax(&sMx[bb * 3 + 0], d);
                atomicMin(&sMn[bb * 3 + 1], h); atomicMax(&sMx[bb * 3 + 1], h);
                if (v.x) { atomicMin(&sMn[bb * 3 + 2], w0 + 0); atomicMax(&sMx[bb * 3 + 2], w0 + 0); }
                if (v.y) { atomicMin(&sMn[bb * 3 + 2], w0 + 1); atomicMax(&sMx[bb * 3 + 2], w0 + 1); }
                if (v.z) { atomicMin(&sMn[bb * 3 + 2], w0 + 2); atomicMax(&sMx[bb * 3 + 2], w0 + 2); }
                if (v.w) { atomicMin(&sMn[bb * 3 + 2], w0 + 3); atomicMax(&sMx[bb * 3 + 2], w0 + 3); }
            }
        }
        __syncthreads();

        __shared__ int sLo[12], sHi[12];
        if (tid < 12) {
            int mn = (sMx[tid] >= 0) ? sMn[tid] : -1;
            int lo, hi;
            bbox_from(mn, sMx[tid], &lo, &hi);
            sLo[tid] = lo; sHi[tid] = hi;
        }
        __syncthreads();

        const float4* PP = (const float4*)pred;
        const float4* TT = (const float4*)truth;
        float fa = 0.0f;
        for (int i = tid; i < N4; i += NT) {
            float4 pv = PP[i];
            float4 tv = TT[i];
            int bb  = i / BATCH4;
            int rem = i - bb * BATCH4;
            int d   = rem / PLANE4;
            int ip  = rem - d * PLANE4;
            int h   = ip / 40;
            int w0  = (ip - h * 40) * 4;
            bool inDH = (d >= sLo[bb * 3]) && (d < sHi[bb * 3]) &&
                        (h >= sLo[bb * 3 + 1]) && (h < sHi[bb * 3 + 1]);
            int loW = sLo[bb * 3 + 2], hiW = sHi[bb * 3 + 2];
            float wx = (inDH && w0 + 0 >= loW && w0 + 0 < hiW) ? 1.0f : 0.01f;
            float wy = (inDH && w0 + 1 >= loW && w0 + 1 < hiW) ? 1.0f : 0.01f;
            float wz = (inDH && w0 + 2 >= loW && w0 + 2 < hiW) ? 1.0f : 0.01f;
            float ww = (inDH && w0 + 3 >= loW && w0 + 3 < hiW) ? 1.0f : 0.01f;
            float dx = pv.x - tv.x, dy = pv.y - tv.y, dz = pv.z - tv.z, dw = pv.w - tv.w;
            fa = fmaf(wx * dx, dx, fa);
            fa = fmaf(wy * dy, dy, fa);
            fa = fmaf(wz * dz, dz, fa);
            fa = fmaf(ww * dw, dw, fa);
        }
        #pragma unroll
        for (int off = 16; off > 0; off >>= 1)
            fa += __shfl_xor_sync(0xFFFFFFFFu, fa, off);
        if (lane == 0) wRed[wid] = (double)fa;
        __syncthreads();
        if (tid == 0) {
            double s = 0.0;
            #pragma unroll
            for (int w = 0; w < 5; w++) s += wRed[w];
            out[0] = (float)(s / TOTAL_ELEMS);
        }
    }

    // ---- reset scratch so the next graph replay starts from a clean state --
    __syncthreads();
    if (tid < 24) ((unsigned char*)g_end)[tid] = 0;
    if (tid < 8)  g_ss8[tid] = 0.0;
    if (tid == 0) g_done = 0u;
}

extern "C" void kernel_launch(void* const* d_in, const int* in_sizes, int n_in,
                              void* d_out, int out_size) {
    const float* y_pred = (const float*)d_in[0];
    const float* y_true = (const float*)d_in[1];
    const int*   mask   = (const int*)d_in[2];
    float* out = (float*)d_out;

    k_all<<<NBLK, NT>>>(y_pred, y_true, mask, out);
}